// round 1
// baseline (speedup 1.0000x reference)
#include <cuda_runtime.h>
#include <math_constants.h>

#define H 128
#define BM 128
#define BK 16
#define TM 8
#define TN 8
#define GATE_CAP 1100032
#define SEG_CAP  65536

// Scratch (no cudaMalloc allowed)
__device__ float d_gate[GATE_CAP];
__device__ int   d_seg_start[SEG_CAP];
__device__ int   d_seg_end[SEG_CAP];

// ---------------------------------------------------------------------------
// Kernel 0: init segment bounds to "empty"
// ---------------------------------------------------------------------------
__global__ void init_bounds_kernel(int B) {
    int b = blockIdx.x * blockDim.x + threadIdx.x;
    if (b < B) { d_seg_start[b] = -1; d_seg_end[b] = -1; }
}

// ---------------------------------------------------------------------------
// Kernel 1: find contiguous segment boundaries in sorted batch_index
// ---------------------------------------------------------------------------
__global__ void bounds_kernel(const int* __restrict__ bi, int N) {
    int n = blockIdx.x * blockDim.x + threadIdx.x;
    if (n >= N) return;
    int b = bi[n];
    if (n == 0 || bi[n - 1] != b) d_seg_start[b] = n;
    if (n == N - 1 || bi[n + 1] != b) d_seg_end[b] = n + 1;
}

// ---------------------------------------------------------------------------
// Kernel 2: fused gate MLP  gate[n] = W2 . silu(x[n] @ W1 + b1) + b2
// Register-tiled FP32 GEMM: block tile 128 nodes x 128 cols, 256 threads,
// each thread computes an 8x8 micro-tile, K tiled by 16.
// ---------------------------------------------------------------------------
__global__ __launch_bounds__(256) void gate_kernel(
    const float* __restrict__ x, const float* __restrict__ W1,
    const float* __restrict__ b1, const float* __restrict__ W2,
    const float* __restrict__ b2, int N)
{
    __shared__ float Xs[BK][BM + 4];   // transposed: [k][m], padded for fl4 align
    __shared__ float Ws[BK][H + 4];    // [k][n]
    __shared__ float sgate[BM];
    __shared__ float sb1[H];
    __shared__ float sW2[H];

    const int tid = threadIdx.x;
    const int tm = tid >> 4;          // 0..15 (node group)
    const int tn = tid & 15;          // 0..15 (col group)
    const long m0 = (long)blockIdx.x * BM;

    if (tid < H) { sb1[tid] = b1[tid]; sW2[tid] = W2[tid]; }
    if (tid < BM) sgate[tid] = 0.f;

    float acc[TM][TN];
#pragma unroll
    for (int i = 0; i < TM; i++)
#pragma unroll
        for (int j = 0; j < TN; j++) acc[i][j] = 0.f;

    // loader mapping
    const int lm = tid >> 1;            // 0..127 node row
    const int lk = (tid & 1) * 8;       // k sub-chunk 0 or 8
    const int wk = tid >> 4;            // 0..15 k row for W1
    const int wn = (tid & 15) * 8;      // col chunk for W1

    for (int k0 = 0; k0 < H; k0 += BK) {
        float4 xa = make_float4(0.f, 0.f, 0.f, 0.f), xb = xa;
        long gm = m0 + lm;
        if (gm < N) {
            const float4* xp = (const float4*)(x + gm * H + k0 + lk);
            xa = xp[0]; xb = xp[1];
        }
        float4 wa = *(const float4*)(W1 + (size_t)(k0 + wk) * H + wn);
        float4 wb = *(const float4*)(W1 + (size_t)(k0 + wk) * H + wn + 4);
        __syncthreads();   // protect prior tile reads (and sgate/sb1 init on iter 0)

        Xs[lk + 0][lm] = xa.x; Xs[lk + 1][lm] = xa.y;
        Xs[lk + 2][lm] = xa.z; Xs[lk + 3][lm] = xa.w;
        Xs[lk + 4][lm] = xb.x; Xs[lk + 5][lm] = xb.y;
        Xs[lk + 6][lm] = xb.z; Xs[lk + 7][lm] = xb.w;
        *(float4*)&Ws[wk][wn]     = wa;
        *(float4*)&Ws[wk][wn + 4] = wb;
        __syncthreads();

#pragma unroll
        for (int k = 0; k < BK; ++k) {
            float xr[TM], wr[TN];
            float4 t0 = *(const float4*)&Xs[k][tm * TM];
            float4 t1 = *(const float4*)&Xs[k][tm * TM + 4];
            xr[0] = t0.x; xr[1] = t0.y; xr[2] = t0.z; xr[3] = t0.w;
            xr[4] = t1.x; xr[5] = t1.y; xr[6] = t1.z; xr[7] = t1.w;
            float4 u0 = *(const float4*)&Ws[k][tn * TN];
            float4 u1 = *(const float4*)&Ws[k][tn * TN + 4];
            wr[0] = u0.x; wr[1] = u0.y; wr[2] = u0.z; wr[3] = u0.w;
            wr[4] = u1.x; wr[5] = u1.y; wr[6] = u1.z; wr[7] = u1.w;
#pragma unroll
            for (int i = 0; i < TM; i++)
#pragma unroll
                for (int j = 0; j < TN; j++)
                    acc[i][j] = fmaf(xr[i], wr[j], acc[i][j]);
        }
    }

    // epilogue: silu + dot with W2, reduce across column groups via shared atomics
    float part[TM];
#pragma unroll
    for (int i = 0; i < TM; i++) {
        float p = 0.f;
#pragma unroll
        for (int j = 0; j < TN; j++) {
            float v = acc[i][j] + sb1[tn * TN + j];
            float hsw = v / (1.f + __expf(-v));   // silu
            p = fmaf(hsw, sW2[tn * TN + j], p);
        }
        part[i] = p;
    }
#pragma unroll
    for (int i = 0; i < TM; i++)
        atomicAdd(&sgate[tm * TM + i], part[i]);
    __syncthreads();

    if (tid < BM) {
        long gm = m0 + tid;
        if (gm < N) d_gate[gm] = sgate[tid] + b2[0];
    }
}

// ---------------------------------------------------------------------------
// Kernel 3: per-segment mean / max / attention readout.
// One block (128 threads = one H column each) per segment; single pass over
// the contiguous node range with an online (streaming) softmax.
// ---------------------------------------------------------------------------
__global__ __launch_bounds__(128) void reduce_kernel(
    const float* __restrict__ x, float* __restrict__ out)
{
    int b = blockIdx.x;
    int j = threadIdx.x;
    int s = d_seg_start[b];
    int e = (s < 0) ? 0 : d_seg_end[b];
    if (s < 0) s = 0;

    float sum = 0.f;
    float mx = -CUDART_INF_F;
    float acc = 0.f;                   // running sum e_i * x_ij (scaled by exp(-m))
    float m = -CUDART_INF_F;           // running gate max
    float denom = 0.f;                 // running sum e_i

    for (int n = s; n < e; ++n) {
        float xv = __ldg(x + (size_t)n * H + j);
        float g  = __ldg((const float*)&d_gate[n]);   // broadcast across block
        sum += xv;
        mx = fmaxf(mx, xv);
        if (g > m) {
            float sc = __expf(m - g);  // exp(-inf)=0 on first node: zeroes state
            denom *= sc;
            acc   *= sc;
            m = g;
        }
        float ev = __expf(g - m);
        denom += ev;
        acc = fmaf(ev, xv, acc);
    }

    int cnt = e - s;
    float* o = out + (size_t)b * (3 * H);
    o[j]         = sum / fmaxf((float)cnt, 1.f);        // mean (0 if empty)
    o[H + j]     = mx;                                  // -inf if empty (jax identity)
    o[2 * H + j] = (cnt > 0) ? (acc / denom) : 0.f;     // attention-weighted sum
}

// ---------------------------------------------------------------------------
extern "C" void kernel_launch(void* const* d_in, const int* in_sizes, int n_in,
                              void* d_out, int out_size) {
    const float* x  = (const float*)d_in[0];
    const float* W1 = (const float*)d_in[1];
    const float* b1 = (const float*)d_in[2];
    const float* W2 = (const float*)d_in[3];
    const float* b2 = (const float*)d_in[4];
    const int*   bi = (const int*)d_in[5];

    const int N = in_sizes[5];            // node count (batch_index length)
    const int B = out_size / (3 * H);     // graph count

    float* out = (float*)d_out;

    init_bounds_kernel<<<(B + 255) / 256, 256>>>(B);
    bounds_kernel<<<(N + 255) / 256, 256>>>(bi, N);
    gate_kernel<<<(N + BM - 1) / BM, 256>>>(x, W1, b1, W2, b2, N);
    reduce_kernel<<<B, H>>>(x, out);
}

// round 3
// speedup vs baseline: 1.6597x; 1.6597x over previous
#include <cuda_runtime.h>
#include <cuda_bf16.h>
#include <math_constants.h>
#include <cstdint>

#define H 128
#define TILE_M 128
#define GATE_CAP 1100032
#define SEG_CAP  65536

// smem layout (bytes); row stride 136 bf16 = 272 B (16B aligned, conflict-free ldmatrix)
#define ROWS_BF 136
#define TILE_BYTES (128 * ROWS_BF * 2)   // 34816
#define OFF_A_HI   0
#define OFF_A_LO   34816
#define OFF_B_HI   69632
#define OFF_B_LO   104448
#define OFF_SGATE2 139264                // 2 x 128 floats = 1024 B
#define OFF_SB1    140288                // 512 B
#define OFF_SW2    140800                // 512 B
#define SMEM_TOTAL 141312

__device__ float d_gate[GATE_CAP];
__device__ int   d_seg_start[SEG_CAP];
__device__ int   d_seg_end[SEG_CAP];
__device__ __nv_bfloat16 d_W1hi[H * H];
__device__ __nv_bfloat16 d_W1lo[H * H];

// ---------------------------------------------------------------------------
__device__ __forceinline__ uint32_t smem_u32(const void* p) {
    uint32_t a;
    asm("{ .reg .u64 t; cvta.to.shared.u64 t, %1; cvt.u32.u64 %0, t; }"
        : "=r"(a) : "l"(p));
    return a;
}
__device__ __forceinline__ void ldsm_x4(uint32_t* r, uint32_t addr) {
    asm volatile("ldmatrix.sync.aligned.m8n8.x4.shared.b16 {%0,%1,%2,%3}, [%4];"
                 : "=r"(r[0]), "=r"(r[1]), "=r"(r[2]), "=r"(r[3]) : "r"(addr));
}
__device__ __forceinline__ void ldsm_x4_t(uint32_t* r, uint32_t addr) {
    asm volatile("ldmatrix.sync.aligned.m8n8.x4.trans.shared.b16 {%0,%1,%2,%3}, [%4];"
                 : "=r"(r[0]), "=r"(r[1]), "=r"(r[2]), "=r"(r[3]) : "r"(addr));
}
__device__ __forceinline__ void mma16816(float* d, const uint32_t* a,
                                         const uint32_t* b) {
    asm volatile(
        "mma.sync.aligned.m16n8k16.row.col.f32.bf16.bf16.f32 "
        "{%0,%1,%2,%3}, {%4,%5,%6,%7}, {%8,%9}, {%0,%1,%2,%3};"
        : "+f"(d[0]), "+f"(d[1]), "+f"(d[2]), "+f"(d[3])
        : "r"(a[0]), "r"(a[1]), "r"(a[2]), "r"(a[3]), "r"(b[0]), "r"(b[1]));
}

// ---------------------------------------------------------------------------
// Segment bounds
// ---------------------------------------------------------------------------
__global__ void init_bounds_kernel(int B) {
    int b = blockIdx.x * blockDim.x + threadIdx.x;
    if (b < B) { d_seg_start[b] = -1; d_seg_end[b] = -1; }
}
__global__ void bounds_kernel(const int* __restrict__ bi, int N) {
    int n = blockIdx.x * blockDim.x + threadIdx.x;
    if (n >= N) return;
    int b = bi[n];
    if (n == 0 || bi[n - 1] != b) d_seg_start[b] = n;
    if (n == N - 1 || bi[n + 1] != b) d_seg_end[b] = n + 1;
}

// ---------------------------------------------------------------------------
// W1 -> bf16 hi/lo split (runs once, 16384 elems)
// ---------------------------------------------------------------------------
__global__ void prep_w1_kernel(const float* __restrict__ W1) {
    int idx = blockIdx.x * blockDim.x + threadIdx.x;
    if (idx >= H * H) return;
    float v = W1[idx];
    __nv_bfloat16 hi = __float2bfloat16(v);
    __nv_bfloat16 lo = __float2bfloat16(v - __bfloat162float(hi));
    d_W1hi[idx] = hi;
    d_W1lo[idx] = lo;
}

// ---------------------------------------------------------------------------
// Gate kernel: gate[n] = W2 . silu(x[n] @ W1 + b1) + b2
// mma.sync m16n8k16 bf16, 3-product hi/lo split, fp32 accumulation.
// One CTA per 128-node tile, 256 threads = 8 warps (4 in M x 2 in N).
// ---------------------------------------------------------------------------
__global__ __launch_bounds__(256, 1) void gate_mma_kernel(
    const float* __restrict__ x, const float* __restrict__ b1,
    const float* __restrict__ W2, const float* __restrict__ b2, int N)
{
    extern __shared__ char smem[];
    const uint32_t sb = smem_u32(smem);
    const int tid = threadIdx.x;
    const int wid = tid >> 5, lane = tid & 31;
    const long m0 = (long)blockIdx.x * TILE_M;

    float* sgate2 = (float*)(smem + OFF_SGATE2);
    float* sb1    = (float*)(smem + OFF_SB1);
    float* sw2    = (float*)(smem + OFF_SW2);
    if (tid < H) { sb1[tid] = b1[tid]; sw2[tid] = W2[tid]; }

    // ---- load X tile (f32 -> bf16 hi/lo) ----
#pragma unroll
    for (int it = 0; it < 16; it++) {
        int idx = it * 256 + tid;
        int r = idx >> 5;
        int c4 = (idx & 31) << 2;
        long gm = m0 + r;
        float4 v = make_float4(0.f, 0.f, 0.f, 0.f);
        if (gm < N) v = *(const float4*)(x + gm * H + c4);
        __nv_bfloat16 h0 = __float2bfloat16(v.x), h1 = __float2bfloat16(v.y);
        __nv_bfloat16 h2 = __float2bfloat16(v.z), h3 = __float2bfloat16(v.w);
        __nv_bfloat16 l0 = __float2bfloat16(v.x - __bfloat162float(h0));
        __nv_bfloat16 l1 = __float2bfloat16(v.y - __bfloat162float(h1));
        __nv_bfloat16 l2 = __float2bfloat16(v.z - __bfloat162float(h2));
        __nv_bfloat16 l3 = __float2bfloat16(v.w - __bfloat162float(h3));
        uint32_t off = (uint32_t)r * (ROWS_BF * 2) + (uint32_t)c4 * 2;
        uint2 uh, ul;
        uh.x = (uint32_t)__bfloat16_as_ushort(h0) | ((uint32_t)__bfloat16_as_ushort(h1) << 16);
        uh.y = (uint32_t)__bfloat16_as_ushort(h2) | ((uint32_t)__bfloat16_as_ushort(h3) << 16);
        ul.x = (uint32_t)__bfloat16_as_ushort(l0) | ((uint32_t)__bfloat16_as_ushort(l1) << 16);
        ul.y = (uint32_t)__bfloat16_as_ushort(l2) | ((uint32_t)__bfloat16_as_ushort(l3) << 16);
        *(uint2*)(smem + OFF_A_HI + off) = uh;
        *(uint2*)(smem + OFF_A_LO + off) = ul;
    }
    // ---- load W1 hi/lo tiles (bf16, already split) ----
#pragma unroll
    for (int it = 0; it < 8; it++) {
        int idx = it * 256 + tid;          // 2048 uint4 per matrix
        int k = idx >> 4;
        int n8 = (idx & 15) << 3;
        uint32_t off = (uint32_t)k * (ROWS_BF * 2) + (uint32_t)n8 * 2;
        *(uint4*)(smem + OFF_B_HI + off) = *(const uint4*)(d_W1hi + idx * 8);
        *(uint4*)(smem + OFF_B_LO + off) = *(const uint4*)(d_W1lo + idx * 8);
    }
    __syncthreads();

    // ---- MMA mainloop ----
    const int warp_m = wid & 3;          // 0..3 -> rows warp_m*32
    const int warp_n = wid >> 2;         // 0..1 -> cols warp_n*64
    float acc[2][8][4];
#pragma unroll
    for (int mi = 0; mi < 2; mi++)
#pragma unroll
        for (int ni = 0; ni < 8; ni++)
#pragma unroll
            for (int r = 0; r < 4; r++) acc[mi][ni][r] = 0.f;

    const uint32_t a_row = (uint32_t)(warp_m * 32 + (lane & 15));
    const uint32_t a_colb = (uint32_t)((lane >> 4) * 8);
    const uint32_t b_rowk = (uint32_t)(lane & 15);
    const uint32_t b_colb = (uint32_t)(warp_n * 64 + (lane >> 4) * 8);

#pragma unroll
    for (int p = 0; p < 3; p++) {
        const uint32_t aBase = sb + ((p == 1) ? OFF_A_LO : OFF_A_HI);
        const uint32_t bBase = sb + ((p == 2) ? OFF_B_LO : OFF_B_HI);
#pragma unroll
        for (int k = 0; k < 8; k++) {
            uint32_t a[2][4];
#pragma unroll
            for (int mi = 0; mi < 2; mi++) {
                uint32_t addr = aBase + (a_row + mi * 16) * (ROWS_BF * 2)
                              + (k * 16 + a_colb) * 2;
                ldsm_x4(a[mi], addr);
            }
            uint32_t b[4][4];   // [ni16][4 regs]: {n-lo k-lo, n-lo k-hi, n-hi k-lo, n-hi k-hi}
#pragma unroll
            for (int nb = 0; nb < 4; nb++) {
                uint32_t addr = bBase + (k * 16 + b_rowk) * (ROWS_BF * 2)
                              + (b_colb + nb * 16) * 2;
                ldsm_x4_t(b[nb], addr);
            }
#pragma unroll
            for (int mi = 0; mi < 2; mi++)
#pragma unroll
                for (int nb = 0; nb < 4; nb++) {
                    mma16816(acc[mi][nb * 2],     a[mi], &b[nb][0]);
                    mma16816(acc[mi][nb * 2 + 1], a[mi], &b[nb][2]);
                }
        }
    }

    // ---- epilogue: silu + dot(W2), warp-level row reduce ----
    float part[2][2] = {{0.f, 0.f}, {0.f, 0.f}};   // [mi][rowhalf]
#pragma unroll
    for (int mi = 0; mi < 2; mi++)
#pragma unroll
        for (int ni = 0; ni < 8; ni++)
#pragma unroll
            for (int r = 0; r < 4; r++) {
                int col = warp_n * 64 + ni * 8 + (lane & 3) * 2 + (r & 1);
                float v = acc[mi][ni][r] + sb1[col];
                float sl = v / (1.f + __expf(-v));
                part[mi][r >> 1] = fmaf(sl, sw2[col], part[mi][r >> 1]);
            }
#pragma unroll
    for (int mi = 0; mi < 2; mi++)
#pragma unroll
        for (int hh = 0; hh < 2; hh++) {
            float p = part[mi][hh];
            p += __shfl_xor_sync(0xFFFFFFFF, p, 1);
            p += __shfl_xor_sync(0xFFFFFFFF, p, 2);
            part[mi][hh] = p;
        }
    if ((lane & 3) == 0) {
#pragma unroll
        for (int mi = 0; mi < 2; mi++)
#pragma unroll
            for (int hh = 0; hh < 2; hh++) {
                int row = warp_m * 32 + mi * 16 + hh * 8 + (lane >> 2);
                sgate2[warp_n * 128 + row] = part[mi][hh];
            }
    }
    __syncthreads();
    if (tid < TILE_M) {
        long gm = m0 + tid;
        if (gm < N)
            d_gate[gm] = sgate2[tid] + sgate2[128 + tid] + __ldg(b2);
    }
}

// ---------------------------------------------------------------------------
// Reduce kernel: per-segment mean/max/attention, 2-way unrolled online softmax
// ---------------------------------------------------------------------------
__global__ __launch_bounds__(128) void reduce_kernel(
    const float* __restrict__ x, float* __restrict__ out)
{
    int b = blockIdx.x;
    int j = threadIdx.x;
    int s = d_seg_start[b];
    int e = (s < 0) ? 0 : d_seg_end[b];
    if (s < 0) s = 0;

    float sum = 0.f, mx = -CUDART_INF_F;
    float m0 = -CUDART_INF_F, dn0 = 0.f, ac0 = 0.f;
    float m1 = -CUDART_INF_F, dn1 = 0.f, ac1 = 0.f;

    int n = s;
    for (; n + 2 <= e; n += 2) {
        float xv0 = __ldg(x + (size_t)n * H + j);
        float g0  = d_gate[n];
        float xv1 = __ldg(x + (size_t)(n + 1) * H + j);
        float g1  = d_gate[n + 1];
        sum += xv0 + xv1;
        mx = fmaxf(mx, fmaxf(xv0, xv1));
        if (g0 > m0) { float sc = __expf(m0 - g0); dn0 *= sc; ac0 *= sc; m0 = g0; }
        float e0 = __expf(g0 - m0); dn0 += e0; ac0 = fmaf(e0, xv0, ac0);
        if (g1 > m1) { float sc = __expf(m1 - g1); dn1 *= sc; ac1 *= sc; m1 = g1; }
        float e1 = __expf(g1 - m1); dn1 += e1; ac1 = fmaf(e1, xv1, ac1);
    }
    if (n < e) {
        float xv = __ldg(x + (size_t)n * H + j);
        float g  = d_gate[n];
        sum += xv; mx = fmaxf(mx, xv);
        if (g > m0) { float sc = __expf(m0 - g); dn0 *= sc; ac0 *= sc; m0 = g; }
        float ev = __expf(g - m0); dn0 += ev; ac0 = fmaf(ev, xv, ac0);
    }

    int cnt = e - s;
    float denom = 0.f, acc = 0.f;
    if (cnt > 0) {
        float M  = fmaxf(m0, m1);
        float s0 = (m0 > -CUDART_INF_F) ? __expf(m0 - M) : 0.f;
        float s1 = (m1 > -CUDART_INF_F) ? __expf(m1 - M) : 0.f;
        denom = dn0 * s0 + dn1 * s1;
        acc   = ac0 * s0 + ac1 * s1;
    }
    float* o = out + (size_t)b * (3 * H);
    o[j]         = sum / fmaxf((float)cnt, 1.f);
    o[H + j]     = mx;
    o[2 * H + j] = (cnt > 0) ? (acc / denom) : 0.f;
}

// ---------------------------------------------------------------------------
extern "C" void kernel_launch(void* const* d_in, const int* in_sizes, int n_in,
                              void* d_out, int out_size) {
    const float* x  = (const float*)d_in[0];
    const float* W1 = (const float*)d_in[1];
    const float* b1 = (const float*)d_in[2];
    const float* W2 = (const float*)d_in[3];
    const float* b2 = (const float*)d_in[4];
    const int*   bi = (const int*)d_in[5];

    const int N = in_sizes[5];
    const int B = out_size / (3 * H);
    float* out = (float*)d_out;

    static int smem_set = 0;
    if (!smem_set) {
        cudaFuncSetAttribute(gate_mma_kernel,
                             cudaFuncAttributeMaxDynamicSharedMemorySize, SMEM_TOTAL);
        smem_set = 1;
    }

    const int numTiles = (N + TILE_M - 1) / TILE_M;

    init_bounds_kernel<<<(B + 255) / 256, 256>>>(B);
    bounds_kernel<<<(N + 255) / 256, 256>>>(bi, N);
    prep_w1_kernel<<<(H * H + 255) / 256, 256>>>(W1);
    gate_mma_kernel<<<numTiles, 256, SMEM_TOTAL>>>(x, b1, W2, b2, N);
    reduce_kernel<<<B, H>>>(x, out);
}